// round 2
// baseline (speedup 1.0000x reference)
#include <cuda_runtime.h>
#include <cstdint>

// DownscaleLabel: label [8,1024,1024] int32 in {-1,0..6} -> out [8,1,64,64].
// Per 16x16 tile: histogram of 8 classes (ignore -1 mapped to class 7 via &7),
// first-max argmax, output -1 if argmax==7 or max_count < 192 (ratio < 0.75).
// Output written as float32 (-1.0f .. 6.0f): the harness's output dtype is
// float32 (int -1 bit pattern 0xFFFFFFFF decoded as NaN in round 1).

static constexpr int H = 1024;
static constexpr int W = 1024;
static constexpr int SCALE = 16;
static constexpr int TILES_PER_IMG = (H / SCALE) * (W / SCALE);  // 4096

__global__ void downscale_label_kernel(const int* __restrict__ label,
                                       float* __restrict__ out,
                                       int n_tiles) {
    const int warp_global = (blockIdx.x * blockDim.x + threadIdx.x) >> 5;
    const int lane = threadIdx.x & 31;
    if (warp_global >= n_tiles) return;

    const int b  = warp_global >> 12;          // / 4096 tiles per image
    const int t  = warp_global & (TILES_PER_IMG - 1);
    const int th = t >> 6;                     // / 64
    const int tw = t & 63;

    // Tile base; one tile row = 16 int32 = 64B = 4 int4 (16B aligned).
    const int4* base = reinterpret_cast<const int4*>(
        label + (size_t)b * H * W + (size_t)th * SCALE * W + tw * SCALE);
    const int row_stride_i4 = W / 4;  // 256

    // Lanes 0-3 cover tile row 0 (contiguous 64B), lanes 4-7 row 1, ...
    const int quad = lane & 3;
    const int row0 = lane >> 2;

    // Packed histogram: acc0 = classes 0..3, acc1 = classes 4..7,
    // 16-bit fields (max 256 per class per tile -> no overflow).
    unsigned long long acc0 = 0ull, acc1 = 0ull;

#pragma unroll
    for (int it = 0; it < 2; ++it) {
        const int row = row0 + it * 8;
        const int4 v = __ldg(base + row * row_stride_i4 + quad);
        const int vals[4] = {v.x, v.y, v.z, v.w};
#pragma unroll
        for (int j = 0; j < 4; ++j) {
            const unsigned c = (unsigned)vals[j] & 7u;  // -1 -> 7, 0..6 -> self
            const unsigned long long inc = 1ull << (16u * (c & 3u));
            if (c & 4u) acc1 += inc; else acc0 += inc;
        }
    }

    // Warp reduction of packed fields.
#pragma unroll
    for (int o = 16; o > 0; o >>= 1) {
        acc0 += __shfl_xor_sync(0xffffffffu, acc0, o);
        acc1 += __shfl_xor_sync(0xffffffffu, acc1, o);
    }

    if (lane == 0) {
        int counts[8];
#pragma unroll
        for (int i = 0; i < 4; ++i) {
            counts[i]     = (int)((acc0 >> (16 * i)) & 0xffffull);
            counts[4 + i] = (int)((acc1 >> (16 * i)) & 0xffffull);
        }
        int best = counts[0], arg = 0;
#pragma unroll
        for (int i = 1; i < 8; ++i) {
            if (counts[i] > best) { best = counts[i]; arg = i; }  // first-max
        }
        // ratio < 0.75  <=>  count < 192 (0.75 * 256 == 192 exactly)
        const int res = (arg == 7 || best < 192) ? -1 : arg;
        out[warp_global] = (float)res;
    }
}

extern "C" void kernel_launch(void* const* d_in, const int* in_sizes, int n_in,
                              void* d_out, int out_size) {
    const int* label = (const int*)d_in[0];
    float* out = (float*)d_out;

    // 8*1024*1024 elements / 256 per tile = 32768 tiles.
    const int n_tiles = in_sizes[0] / (SCALE * SCALE);

    const int threads = 256;                 // 8 warps -> 8 tiles per block
    const int warps_per_block = threads / 32;
    const int blocks = (n_tiles + warps_per_block - 1) / warps_per_block;

    downscale_label_kernel<<<blocks, threads>>>(label, out, n_tiles);
}

// round 3
// speedup vs baseline: 1.4301x; 1.4301x over previous
#include <cuda_runtime.h>
#include <cstdint>

// DownscaleLabel: label [8,1024,1024] int32 in {-1,0..6} -> out [8,1,64,64] f32.
// Per 16x16 tile: 8-class histogram (ignore -1 -> class 7 via &7), first-max
// argmax, -1 if argmax==7 or max_count < 192 (== ratio < 0.75, exact).
//
// Layout: 1 warp = 8 horizontally-adjacent tiles. lane -> (tile = lane>>2,
// quad = lane&3). Each thread: 16 int4 loads (one per tile row), i.e. 64 px.
// Every load instruction covers a contiguous 512B row segment (perfect
// coalescing). Histogram: 64-bit acc, 8x8-bit class fields (max 64/thread).
// Reduce across the 4 quad-lanes: 1 round in 8-bit fields (max 128), widen to
// 16-bit even/odd fields, 1 more round (max 256). Lanes with quad==0 extract
// + argmax their tile in parallel (8 tiles at once).

static constexpr int H = 1024;
static constexpr int W = 1024;
static constexpr int SCALE = 16;
static constexpr int TILES_PER_IMG = (H / SCALE) * (W / SCALE);  // 4096
static constexpr int WARPS_PER_IMG = TILES_PER_IMG / 8;          // 512

__global__ void downscale_label_kernel(const int* __restrict__ label,
                                       float* __restrict__ out,
                                       int n_warps) {
    const int wg   = (blockIdx.x * blockDim.x + threadIdx.x) >> 5;
    const int lane = threadIdx.x & 31;
    if (wg >= n_warps) return;

    const int b    = wg >> 9;              // / WARPS_PER_IMG
    const int wi   = wg & (WARPS_PER_IMG - 1);
    const int th   = wi >> 3;              // tile row (64 rows, 8 warps/row)
    const int twg  = wi & 7;               // group of 8 tiles

    // Per-lane base: lane*16 bytes into the 512B warp row segment.
    // int4 index within an image row: twg*32 + lane*4 ints = twg*8 + lane (int4)
    const int4* p = reinterpret_cast<const int4*>(label)
                    + ((size_t)b << 18)            // b * 1024*1024 / 4
                    + ((size_t)th << 12)           // th * 16 rows * 256 int4
                    + (twg << 3) + lane;
    const int row_i4 = W / 4;                      // 256 int4 per image row

    // Two interleaved 8x8-bit packed accumulators (halve the dep chain).
    unsigned long long a0 = 0ull, a1 = 0ull;

#pragma unroll
    for (int r = 0; r < 16; ++r) {
        const int4 v = __ldg(p + r * row_i4);
        a0 += 1ull << ((((unsigned)v.x & 7u) << 3));
        a1 += 1ull << ((((unsigned)v.y & 7u) << 3));
        a0 += 1ull << ((((unsigned)v.z & 7u) << 3));
        a1 += 1ull << ((((unsigned)v.w & 7u) << 3));
    }
    unsigned long long acc = a0 + a1;              // max 64 per 8-bit field

    // Reduce over the 4 quad lanes of each tile.
    acc += __shfl_xor_sync(0xffffffffu, acc, 1);   // max 128, still fits 8-bit
    // Widen: even classes (0,2,4,6) and odd classes (1,3,5,7) -> 16-bit fields
    unsigned long long e = acc & 0x00FF00FF00FF00FFull;
    unsigned long long o = (acc >> 8) & 0x00FF00FF00FF00FFull;
    e += __shfl_xor_sync(0xffffffffu, e, 2);       // max 256 in 16-bit
    o += __shfl_xor_sync(0xffffffffu, o, 2);

    if ((lane & 3) == 0) {
        int counts[8];
#pragma unroll
        for (int i = 0; i < 4; ++i) {
            counts[2 * i]     = (int)((e >> (16 * i)) & 0xffffull);
            counts[2 * i + 1] = (int)((o >> (16 * i)) & 0xffffull);
        }
        int best = counts[0], arg = 0;
#pragma unroll
        for (int i = 1; i < 8; ++i) {
            if (counts[i] > best) { best = counts[i]; arg = i; }  // first-max
        }
        // ratio < 0.75  <=>  count < 192 (0.75 * 256 == 192 exactly)
        const int res = (arg == 7 || best < 192) ? -1 : arg;

        const int tw = (twg << 3) + (lane >> 2);
        out[b * TILES_PER_IMG + th * 64 + tw] = (float)res;
    }
}

extern "C" void kernel_launch(void* const* d_in, const int* in_sizes, int n_in,
                              void* d_out, int out_size) {
    const int* label = (const int*)d_in[0];
    float* out = (float*)d_out;

    // 8*1024*1024 px / 256 px per tile / 8 tiles per warp = 4096 warps.
    const int n_tiles = in_sizes[0] / (SCALE * SCALE);
    const int n_warps = n_tiles / 8;

    const int threads = 128;                 // 4 warps/block -> 1024 blocks
    const int blocks = (n_warps * 32 + threads - 1) / threads;

    downscale_label_kernel<<<blocks, threads>>>(label, out, n_warps);
}